// round 5
// baseline (speedup 1.0000x reference)
#include <cuda_runtime.h>
#include <math.h>

#define N_NODES 50000
#define N_EDGES 800000
#define D_IN    128
#define D1      150
#define D1P     160   // h1 padded stride (cols 150..159 = 0)
#define D2      100
#define DPS     200   // packed p|s stride: p = [0,100), s = [100,200)
#define H2P     112   // h2 padded stride (cols 100..111 = 0)
#define D_OUT   64

// ---------------- scratch (device globals) -----------------------------------
__device__ int   g_deg_out_i[N_NODES];
__device__ int   g_deg_in_i [N_NODES];
__device__ int   g_rowoff[N_NODES];
__device__ int   g_fill  [N_NODES];
__device__ int   g_total;
__device__ int   g_csr[N_EDGES];
__device__ float g_norm_out[N_NODES];

__device__ float g_W1p[128 * 160];   // W1 cols padded 150->160
__device__ float g_b1p[160];
__device__ float g_W2p[160 * 200];   // [Wn | Ws] packed, K padded 150->160
__device__ float g_W3p[128 * 64];    // W3 K padded 100->128 (rows 100+ zero)

__device__ float g_agg[(size_t)N_NODES * D_IN];
__device__ float g_h1 [(size_t)N_NODES * D1P];
__device__ float g_ps [(size_t)N_NODES * DPS];
__device__ float g_h2 [(size_t)N_NODES * H2P];

__device__ __forceinline__ float elu(float v) { return v > 0.f ? v : expm1f(v); }

// ---------------- prep: pad weights, zero counters ---------------------------
__global__ void prep_kernel(const float* __restrict__ W1, const float* __restrict__ b1,
                            const float* __restrict__ Wn, const float* __restrict__ Ws,
                            const float* __restrict__ W3) {
    int stride = gridDim.x * blockDim.x;
    int t0 = blockIdx.x * blockDim.x + threadIdx.x;
    for (int i = t0; i < 128 * 160; i += stride) {
        int k = i / 160, c = i % 160;
        g_W1p[i] = (c < D1) ? W1[k * D1 + c] : 0.f;
    }
    for (int i = t0; i < 160; i += stride) g_b1p[i] = (i < D1) ? b1[i] : 0.f;
    for (int i = t0; i < 160 * 200; i += stride) {
        int k = i / 200, c = i % 200;
        float v = 0.f;
        if (k < D1) v = (c < D2) ? Wn[k * D2 + c] : Ws[k * D2 + (c - D2)];
        g_W2p[i] = v;
    }
    for (int i = t0; i < 128 * 64; i += stride) {
        int k = i / 64, c = i % 64;
        g_W3p[i] = (k < D2) ? W3[k * 64 + c] : 0.f;
    }
    for (int i = t0; i < N_NODES; i += stride) {
        g_deg_out_i[i] = 0;
        g_deg_in_i[i]  = 0;
    }
    if (t0 == 0) g_total = 0;
}

// ---------------- degrees ----------------------------------------------------
__global__ void degree_kernel(const int* __restrict__ src, const int* __restrict__ dst) {
    int i = blockIdx.x * blockDim.x + threadIdx.x;
    if (i < N_EDGES) {
        atomicAdd(&g_deg_out_i[src[i]], 1);
        atomicAdd(&g_deg_in_i [dst[i]], 1);
    }
}

// ---------------- row offsets via warp-aggregated atomic ---------------------
__global__ void rowoff_kernel() {
    int i = blockIdx.x * blockDim.x + threadIdx.x;
    int lane = threadIdx.x & 31;
    int d = (i < N_NODES) ? g_deg_in_i[i] : 0;
    int x = d;
#pragma unroll
    for (int off = 1; off < 32; off <<= 1) {
        int t = __shfl_up_sync(0xffffffffu, x, off);
        if (lane >= off) x += t;
    }
    int excl = x - d;
    int total = __shfl_sync(0xffffffffu, x, 31);
    int base = 0;
    if (lane == 0) base = atomicAdd(&g_total, total);
    base = __shfl_sync(0xffffffffu, base, 0);
    if (i < N_NODES) {
        int o = base + excl;
        g_rowoff[i] = o;
        g_fill[i]   = o;
        g_norm_out[i] = rsqrtf(fmaxf((float)g_deg_out_i[i], 1.f));
    }
}

__global__ void bucket_kernel(const int* __restrict__ src, const int* __restrict__ dst) {
    int i = blockIdx.x * blockDim.x + threadIdx.x;
    if (i < N_EDGES) {
        int pos = atomicAdd(&g_fill[dst[i]], 1);
        g_csr[pos] = src[i];
    }
}

// ---------------- gather 1: agg[d] = norm_in[d] * sum x[s]*norm_out[s] -------
// one warp per node; broadcast csr loads, 4-way unroll for MLP
__global__ void gather1_kernel(const float* __restrict__ x) {
    int w    = (blockIdx.x * blockDim.x + threadIdx.x) >> 5;
    int lane = threadIdx.x & 31;
    if (w >= N_NODES) return;
    int beg = g_rowoff[w];
    int cnt = g_deg_in_i[w];
    float4 acc = make_float4(0.f, 0.f, 0.f, 0.f);
    int j = 0;
    for (; j + 4 <= cnt; j += 4) {
        int s0 = __ldg(&g_csr[beg + j]);
        int s1 = __ldg(&g_csr[beg + j + 1]);
        int s2 = __ldg(&g_csr[beg + j + 2]);
        int s3 = __ldg(&g_csr[beg + j + 3]);
        float n0 = __ldg(&g_norm_out[s0]);
        float n1 = __ldg(&g_norm_out[s1]);
        float n2 = __ldg(&g_norm_out[s2]);
        float n3 = __ldg(&g_norm_out[s3]);
        float4 v0 = __ldg((const float4*)(x + (size_t)s0 * D_IN) + lane);
        float4 v1 = __ldg((const float4*)(x + (size_t)s1 * D_IN) + lane);
        float4 v2 = __ldg((const float4*)(x + (size_t)s2 * D_IN) + lane);
        float4 v3 = __ldg((const float4*)(x + (size_t)s3 * D_IN) + lane);
        acc.x = fmaf(v0.x, n0, acc.x); acc.y = fmaf(v0.y, n0, acc.y);
        acc.z = fmaf(v0.z, n0, acc.z); acc.w = fmaf(v0.w, n0, acc.w);
        acc.x = fmaf(v1.x, n1, acc.x); acc.y = fmaf(v1.y, n1, acc.y);
        acc.z = fmaf(v1.z, n1, acc.z); acc.w = fmaf(v1.w, n1, acc.w);
        acc.x = fmaf(v2.x, n2, acc.x); acc.y = fmaf(v2.y, n2, acc.y);
        acc.z = fmaf(v2.z, n2, acc.z); acc.w = fmaf(v2.w, n2, acc.w);
        acc.x = fmaf(v3.x, n3, acc.x); acc.y = fmaf(v3.y, n3, acc.y);
        acc.z = fmaf(v3.z, n3, acc.z); acc.w = fmaf(v3.w, n3, acc.w);
    }
    for (; j < cnt; j++) {
        int s0 = __ldg(&g_csr[beg + j]);
        float n0 = __ldg(&g_norm_out[s0]);
        float4 v0 = __ldg((const float4*)(x + (size_t)s0 * D_IN) + lane);
        acc.x = fmaf(v0.x, n0, acc.x); acc.y = fmaf(v0.y, n0, acc.y);
        acc.z = fmaf(v0.z, n0, acc.z); acc.w = fmaf(v0.w, n0, acc.w);
    }
    float nin = rsqrtf(fmaxf((float)cnt, 1.f));
    acc.x *= nin; acc.y *= nin; acc.z *= nin; acc.w *= nin;
    ((float4*)(g_agg + (size_t)w * D_IN))[lane] = acc;
}

// ---------------- GEMM1: h1 = ELU(agg @ W1p + b1p)  [N,128]->[N,160] ---------
// 160 thr: rg 8 x cg 20, TM=8, TN=8
__global__ __launch_bounds__(160, 3) void gemm1_kernel() {
    __shared__ float As[64][36];
    __shared__ float Bs[32][160];
    int tid = threadIdx.x;
    int row0 = blockIdx.x * 64;
    int rg = tid / 20, cg = tid % 20;
    float acc[8][8];
#pragma unroll
    for (int i = 0; i < 8; i++)
#pragma unroll
        for (int j = 0; j < 8; j++) acc[i][j] = 0.f;

    for (int k0 = 0; k0 < 128; k0 += 32) {
        for (int idx = tid; idx < 512; idx += 160) {
            int r = idx >> 3, c4 = idx & 7;
            float4 v = make_float4(0.f, 0.f, 0.f, 0.f);
            if (row0 + r < N_NODES)
                v = *(const float4*)&g_agg[(size_t)(row0 + r) * D_IN + k0 + c4 * 4];
            *(float4*)&As[r][c4 * 4] = v;
        }
        for (int idx = tid; idx < 1280; idx += 160) {
            int r = idx / 40, c4 = idx % 40;
            *(float4*)&Bs[r][c4 * 4] = *(const float4*)&g_W1p[(k0 + r) * 160 + c4 * 4];
        }
        __syncthreads();
#pragma unroll
        for (int kk = 0; kk < 32; kk += 4) {
            float4 a4[8];
#pragma unroll
            for (int i = 0; i < 8; i++) a4[i] = *(const float4*)&As[rg * 8 + i][kk];
#pragma unroll
            for (int q = 0; q < 4; q++) {
                float4 b0 = *(const float4*)&Bs[kk + q][cg * 8];
                float4 b1 = *(const float4*)&Bs[kk + q][cg * 8 + 4];
                float bv[8] = {b0.x, b0.y, b0.z, b0.w, b1.x, b1.y, b1.z, b1.w};
#pragma unroll
                for (int i = 0; i < 8; i++) {
                    float a = (q == 0) ? a4[i].x : (q == 1) ? a4[i].y : (q == 2) ? a4[i].z : a4[i].w;
#pragma unroll
                    for (int j = 0; j < 8; j++) acc[i][j] = fmaf(a, bv[j], acc[i][j]);
                }
            }
        }
        __syncthreads();
    }
#pragma unroll
    for (int i = 0; i < 8; i++) {
        int g = row0 + rg * 8 + i;
        if (g >= N_NODES) continue;
        float4 o0, o1;
        const float* bb = &g_b1p[cg * 8];
        o0.x = elu(acc[i][0] + bb[0]); o0.y = elu(acc[i][1] + bb[1]);
        o0.z = elu(acc[i][2] + bb[2]); o0.w = elu(acc[i][3] + bb[3]);
        o1.x = elu(acc[i][4] + bb[4]); o1.y = elu(acc[i][5] + bb[5]);
        o1.z = elu(acc[i][6] + bb[6]); o1.w = elu(acc[i][7] + bb[7]);
        float* hp = &g_h1[(size_t)g * D1P + cg * 8];
        *(float4*)hp = o0;
        *(float4*)(hp + 4) = o1;
    }
}

// ---------------- GEMM2 fused: ps = h1 @ [Wn|Ws]  [N,160]->[N,200] -----------
// 160 thr: rg 8 x cg 20, TM=8, TN=10 (float2 B loads for alignment)
__global__ __launch_bounds__(160, 3) void gemm2_kernel() {
    __shared__ float As[64][36];
    __shared__ float Bs[32][200];
    int tid = threadIdx.x;
    int row0 = blockIdx.x * 64;
    int rg = tid / 20, cg = tid % 20;
    float acc[8][10];
#pragma unroll
    for (int i = 0; i < 8; i++)
#pragma unroll
        for (int j = 0; j < 10; j++) acc[i][j] = 0.f;

    for (int k0 = 0; k0 < 160; k0 += 32) {
        for (int idx = tid; idx < 512; idx += 160) {
            int r = idx >> 3, c4 = idx & 7;
            float4 v = make_float4(0.f, 0.f, 0.f, 0.f);
            if (row0 + r < N_NODES)
                v = *(const float4*)&g_h1[(size_t)(row0 + r) * D1P + k0 + c4 * 4];
            *(float4*)&As[r][c4 * 4] = v;
        }
        for (int idx = tid; idx < 1600; idx += 160) {
            int r = idx / 50, c4 = idx % 50;
            *(float4*)&Bs[r][c4 * 4] = *(const float4*)&g_W2p[(k0 + r) * 200 + c4 * 4];
        }
        __syncthreads();
#pragma unroll
        for (int kk = 0; kk < 32; kk += 4) {
            float4 a4[8];
#pragma unroll
            for (int i = 0; i < 8; i++) a4[i] = *(const float4*)&As[rg * 8 + i][kk];
#pragma unroll
            for (int q = 0; q < 4; q++) {
                const float* bp = &Bs[kk + q][cg * 10];
                float bv[10];
#pragma unroll
                for (int t = 0; t < 5; t++) {
                    float2 v = *(const float2*)(bp + t * 2);
                    bv[t * 2] = v.x; bv[t * 2 + 1] = v.y;
                }
#pragma unroll
                for (int i = 0; i < 8; i++) {
                    float a = (q == 0) ? a4[i].x : (q == 1) ? a4[i].y : (q == 2) ? a4[i].z : a4[i].w;
#pragma unroll
                    for (int j = 0; j < 10; j++) acc[i][j] = fmaf(a, bv[j], acc[i][j]);
                }
            }
        }
        __syncthreads();
    }
#pragma unroll
    for (int i = 0; i < 8; i++) {
        int g = row0 + rg * 8 + i;
        if (g >= N_NODES) continue;
        float* op = &g_ps[(size_t)g * DPS + cg * 10];
#pragma unroll
        for (int t = 0; t < 5; t++) {
            float2 v; v.x = acc[i][t * 2]; v.y = acc[i][t * 2 + 1];
            *(float2*)(op + t * 2) = v;
        }
    }
}

// ---------------- gather 2 + SAGE epilogue: h2 = ELU(s + mean(p) + b2) -------
__global__ void gather2_kernel(const float* __restrict__ b2) {
    int w    = (blockIdx.x * blockDim.x + threadIdx.x) >> 5;
    int lane = threadIdx.x & 31;
    if (w >= N_NODES) return;
    int beg = g_rowoff[w];
    int cnt = g_deg_in_i[w];
    bool act = lane < (D2 / 4);   // 25 data lanes
    float4 acc = make_float4(0.f, 0.f, 0.f, 0.f);
    int j = 0;
    for (; j + 4 <= cnt; j += 4) {
        int s0 = __ldg(&g_csr[beg + j]);
        int s1 = __ldg(&g_csr[beg + j + 1]);
        int s2 = __ldg(&g_csr[beg + j + 2]);
        int s3 = __ldg(&g_csr[beg + j + 3]);
        if (act) {
            float4 v0 = __ldg((const float4*)(g_ps + (size_t)s0 * DPS) + lane);
            float4 v1 = __ldg((const float4*)(g_ps + (size_t)s1 * DPS) + lane);
            float4 v2 = __ldg((const float4*)(g_ps + (size_t)s2 * DPS) + lane);
            float4 v3 = __ldg((const float4*)(g_ps + (size_t)s3 * DPS) + lane);
            acc.x += v0.x + v1.x + v2.x + v3.x;
            acc.y += v0.y + v1.y + v2.y + v3.y;
            acc.z += v0.z + v1.z + v2.z + v3.z;
            acc.w += v0.w + v1.w + v2.w + v3.w;
        }
    }
    for (; j < cnt; j++) {
        int s0 = __ldg(&g_csr[beg + j]);
        if (act) {
            float4 v0 = __ldg((const float4*)(g_ps + (size_t)s0 * DPS) + lane);
            acc.x += v0.x; acc.y += v0.y; acc.z += v0.z; acc.w += v0.w;
        }
    }
    float4 o = make_float4(0.f, 0.f, 0.f, 0.f);
    if (act) {
        float invd = 1.f / fmaxf((float)cnt, 1.f);
        float4 sv = *(const float4*)(g_ps + (size_t)w * DPS + D2 + lane * 4);
        float4 bv = *(const float4*)(b2 + lane * 4);
        o.x = elu(acc.x * invd + sv.x + bv.x);
        o.y = elu(acc.y * invd + sv.y + bv.y);
        o.z = elu(acc.z * invd + sv.z + bv.z);
        o.w = elu(acc.w * invd + sv.w + bv.w);
    }
    if (lane < H2P / 4)
        *(float4*)(g_h2 + (size_t)w * H2P + lane * 4) = o;
}

// ---------------- GEMM3: out = ELU(h2 @ W3p + b3)  [N,112]->[N,64] -----------
// 128 thr: rg 16 x cg 8, BM=128, TM=8, TN=8, K tiles 32/32/32/16
__global__ __launch_bounds__(128, 3) void gemm3_kernel(const float* __restrict__ b3,
                                                       float* __restrict__ out) {
    __shared__ float As[128][36];
    __shared__ float Bs[32][64];
    int tid = threadIdx.x;
    int row0 = blockIdx.x * 128;
    int rg = tid / 8, cg = tid % 8;
    float acc[8][8];
#pragma unroll
    for (int i = 0; i < 8; i++)
#pragma unroll
        for (int j = 0; j < 8; j++) acc[i][j] = 0.f;

    for (int k0 = 0; k0 < 128; k0 += 32) {
        for (int idx = tid; idx < 1024; idx += 128) {
            int r = idx >> 3, c4 = idx & 7;
            int kc = (k0 >> 2) + c4;   // global float4 col
            float4 v = make_float4(0.f, 0.f, 0.f, 0.f);
            if (row0 + r < N_NODES && kc < H2P / 4)
                v = *(const float4*)&g_h2[(size_t)(row0 + r) * H2P + kc * 4];
            *(float4*)&As[r][c4 * 4] = v;
        }
        for (int idx = tid; idx < 512; idx += 128) {
            int r = idx >> 4, c4 = idx & 15;
            *(float4*)&Bs[r][c4 * 4] = *(const float4*)&g_W3p[(k0 + r) * 64 + c4 * 4];
        }
        __syncthreads();
#pragma unroll
        for (int kk = 0; kk < 32; kk += 4) {
            float4 a4[8];
#pragma unroll
            for (int i = 0; i < 8; i++) a4[i] = *(const float4*)&As[rg * 8 + i][kk];
#pragma unroll
            for (int q = 0; q < 4; q++) {
                float4 b0 = *(const float4*)&Bs[kk + q][cg * 8];
                float4 b1 = *(const float4*)&Bs[kk + q][cg * 8 + 4];
                float bv[8] = {b0.x, b0.y, b0.z, b0.w, b1.x, b1.y, b1.z, b1.w};
#pragma unroll
                for (int i = 0; i < 8; i++) {
                    float a = (q == 0) ? a4[i].x : (q == 1) ? a4[i].y : (q == 2) ? a4[i].z : a4[i].w;
#pragma unroll
                    for (int j = 0; j < 8; j++) acc[i][j] = fmaf(a, bv[j], acc[i][j]);
                }
            }
        }
        __syncthreads();
    }
#pragma unroll
    for (int i = 0; i < 8; i++) {
        int g = row0 + rg * 8 + i;
        if (g >= N_NODES) continue;
        const float* bb = &b3[cg * 8];
        float4 o0, o1;
        o0.x = elu(acc[i][0] + bb[0]); o0.y = elu(acc[i][1] + bb[1]);
        o0.z = elu(acc[i][2] + bb[2]); o0.w = elu(acc[i][3] + bb[3]);
        o1.x = elu(acc[i][4] + bb[4]); o1.y = elu(acc[i][5] + bb[5]);
        o1.z = elu(acc[i][6] + bb[6]); o1.w = elu(acc[i][7] + bb[7]);
        float* op = &out[(size_t)g * D_OUT + cg * 8];
        *(float4*)op = o0;
        *(float4*)(op + 4) = o1;
    }
}

// ---------------- launch -----------------------------------------------------
extern "C" void kernel_launch(void* const* d_in, const int* in_sizes, int n_in,
                              void* d_out, int out_size) {
    const float* x   = (const float*)d_in[0];
    const int*   src = (const int*)d_in[1];
    const int*   dst = (const int*)d_in[2];
    const float* W1  = (const float*)d_in[3];
    const float* b1  = (const float*)d_in[4];
    const float* Wn  = (const float*)d_in[5];
    const float* Ws  = (const float*)d_in[6];
    const float* b2  = (const float*)d_in[7];
    const float* W3  = (const float*)d_in[8];
    const float* b3  = (const float*)d_in[9];
    float* out = (float*)d_out;

    const int ROW_BLOCKS  = (N_NODES + 63) / 64;        // 782
    const int EDGE_BLOCKS = (N_EDGES + 255) / 256;      // 3125
    const int WARP_BLOCKS = (N_NODES * 32 + 255) / 256; // 6250

    prep_kernel<<<256, 256>>>(W1, b1, Wn, Ws, W3);
    degree_kernel<<<EDGE_BLOCKS, 256>>>(src, dst);
    rowoff_kernel<<<(N_NODES + 255) / 256, 256>>>();
    bucket_kernel<<<EDGE_BLOCKS, 256>>>(src, dst);
    gather1_kernel<<<WARP_BLOCKS, 256>>>(x);
    gemm1_kernel<<<ROW_BLOCKS, 160>>>();
    gemm2_kernel<<<ROW_BLOCKS, 160>>>();
    gather2_kernel<<<WARP_BLOCKS, 256>>>(b2);
    gemm3_kernel<<<(N_NODES + 127) / 128, 128>>>(b3, out);
}

// round 6
// speedup vs baseline: 1.5158x; 1.5158x over previous
#include <cuda_runtime.h>
#include <math.h>

#define N_NODES 50000
#define N_EDGES 800000
#define D_IN    128
#define D1      150
#define D1P     152
#define D2      100
#define D_OUT   64

// ---------------- scratch (device globals) -----------------------------------
__device__ int   g_deg_out_i[N_NODES];
__device__ int   g_deg_in_i [N_NODES];
__device__ int   g_rowoff[N_NODES];
__device__ int   g_fill  [N_NODES];
__device__ int   g_total;
__device__ int   g_csr[N_EDGES];
__device__ float g_norm_out[N_NODES];

__device__ float g_agg[(size_t)N_NODES * D_IN];   // (A x) * norms, ready for W1
__device__ float g_h1 [(size_t)N_NODES * D1P];    // ELU(GraphConv), padded 152
__device__ float g_p  [(size_t)N_NODES * D2];     // h1 @ Wn
__device__ float g_s  [(size_t)N_NODES * D2];     // h1 @ Ws
__device__ float g_h2 [(size_t)N_NODES * D2];     // SAGE output

__device__ __forceinline__ float elu(float v) { return v > 0.f ? v : expm1f(v); }

// ---------------- zero counters ----------------------------------------------
__global__ void zero_kernel() {
    int stride = gridDim.x * blockDim.x;
    for (int i = blockIdx.x * blockDim.x + threadIdx.x; i < N_NODES; i += stride) {
        g_deg_out_i[i] = 0;
        g_deg_in_i[i]  = 0;
    }
    if (blockIdx.x == 0 && threadIdx.x == 0) g_total = 0;
}

// ---------------- degrees ----------------------------------------------------
__global__ void degree_kernel(const int* __restrict__ src, const int* __restrict__ dst) {
    int i = blockIdx.x * blockDim.x + threadIdx.x;
    if (i < N_EDGES) {
        atomicAdd(&g_deg_out_i[src[i]], 1);
        atomicAdd(&g_deg_in_i [dst[i]], 1);
    }
}

// ---------------- row offsets via warp-aggregated atomic ---------------------
__global__ void rowoff_kernel() {
    int i = blockIdx.x * blockDim.x + threadIdx.x;
    int lane = threadIdx.x & 31;
    int d = (i < N_NODES) ? g_deg_in_i[i] : 0;
    int x = d;
#pragma unroll
    for (int off = 1; off < 32; off <<= 1) {
        int t = __shfl_up_sync(0xffffffffu, x, off);
        if (lane >= off) x += t;
    }
    int excl = x - d;
    int total = __shfl_sync(0xffffffffu, x, 31);
    int base = 0;
    if (lane == 0) base = atomicAdd(&g_total, total);
    base = __shfl_sync(0xffffffffu, base, 0);
    if (i < N_NODES) {
        int o = base + excl;
        g_rowoff[i] = o;
        g_fill[i]   = o;
        g_norm_out[i] = rsqrtf(fmaxf((float)g_deg_out_i[i], 1.f));
    }
}

__global__ void bucket_kernel(const int* __restrict__ src, const int* __restrict__ dst) {
    int i = blockIdx.x * blockDim.x + threadIdx.x;
    if (i < N_EDGES) {
        int pos = atomicAdd(&g_fill[dst[i]], 1);
        g_csr[pos] = src[i];
    }
}

// ---------------- gather 1: agg[d] = norm_in[d] * sum x[s]*norm_out[s] -------
// one warp per node, lane handles 4 contiguous floats of the 128-float row
__global__ void gather1_kernel(const float* __restrict__ x) {
    int w    = (blockIdx.x * blockDim.x + threadIdx.x) >> 5;
    int lane = threadIdx.x & 31;
    if (w >= N_NODES) return;
    int beg = g_rowoff[w];
    int cnt = g_deg_in_i[w];
    float4 acc = make_float4(0.f, 0.f, 0.f, 0.f);
    for (int base = 0; base < cnt; base += 32) {
        int idx = base + lane;
        int s = 0; float ns = 0.f;
        if (idx < cnt) { s = g_csr[beg + idx]; ns = g_norm_out[s]; }
        int m = min(32, cnt - base);
        for (int j = 0; j < m; j++) {
            int   sj  = __shfl_sync(0xffffffffu, s,  j);
            float nsj = __shfl_sync(0xffffffffu, ns, j);
            float4 v = __ldg((const float4*)(x + (size_t)sj * D_IN) + lane);
            acc.x = fmaf(v.x, nsj, acc.x);
            acc.y = fmaf(v.y, nsj, acc.y);
            acc.z = fmaf(v.z, nsj, acc.z);
            acc.w = fmaf(v.w, nsj, acc.w);
        }
    }
    float nin = rsqrtf(fmaxf((float)cnt, 1.f));
    acc.x *= nin; acc.y *= nin; acc.z *= nin; acc.w *= nin;
    ((float4*)(g_agg + (size_t)w * D_IN))[lane] = acc;
}

// ---------------- GEMM1: h1 = ELU(agg @ W1 + b1)  [N,128]->[N,150] -----------
__global__ __launch_bounds__(240) void gemm1_kernel(const float* __restrict__ W1,
                                                    const float* __restrict__ b1) {
    __shared__ float as[64 * 132];
    int tid = threadIdx.x;
    int row0 = blockIdx.x * 64;
    for (int idx = tid; idx < 64 * (D_IN / 4); idx += 240) {
        int r = idx >> 5, c4 = idx & 31;
        int g = row0 + r;
        float4 v = make_float4(0.f, 0.f, 0.f, 0.f);
        if (g < N_NODES) v = ((const float4*)(g_agg + (size_t)g * D_IN))[c4];
        *(float4*)&as[r * 132 + (c4 << 2)] = v;
    }
    __syncthreads();
    int cg = tid % 30, rg = tid / 30;
    float acc[8][5];
#pragma unroll
    for (int i = 0; i < 8; i++)
#pragma unroll
        for (int j = 0; j < 5; j++) acc[i][j] = 0.f;

#pragma unroll 4
    for (int k = 0; k < D_IN; k++) {
        float wv[5];
#pragma unroll
        for (int j = 0; j < 5; j++) wv[j] = __ldg(&W1[k * D1 + cg + 30 * j]);
#pragma unroll
        for (int i = 0; i < 8; i++) {
            float av = as[(rg * 8 + i) * 132 + k];
#pragma unroll
            for (int j = 0; j < 5; j++) acc[i][j] = fmaf(av, wv[j], acc[i][j]);
        }
    }
#pragma unroll
    for (int i = 0; i < 8; i++) {
        int g = row0 + rg * 8 + i;
        if (g >= N_NODES) continue;
#pragma unroll
        for (int j = 0; j < 5; j++) {
            int c = cg + 30 * j;
            g_h1[(size_t)g * D1P + c] = elu(acc[i][j] + b1[c]);
        }
    }
}

// ---------------- GEMM2 merged: p = h1@Wn, s = h1@Ws  [N,150]->[N,100]x2 -----
// R3 style: A-tile in smem (loaded once for BOTH products), W streamed via __ldg
// 160 thr: rg 8 x cg 20, TM=8, TN=5 per product
__global__ __launch_bounds__(160) void gemm2_kernel(const float* __restrict__ Wn,
                                                    const float* __restrict__ Ws) {
    __shared__ float as[64 * D1P];
    int tid = threadIdx.x;
    int row0 = blockIdx.x * 64;
    for (int idx = tid; idx < 64 * (D1P / 4); idx += 160) {
        int r = idx / 38, c4 = idx % 38;
        int g = row0 + r;
        float4 v = make_float4(0.f, 0.f, 0.f, 0.f);
        if (g < N_NODES) v = ((const float4*)(g_h1 + (size_t)g * D1P))[c4];
        *(float4*)&as[r * D1P + c4 * 4] = v;
    }
    __syncthreads();
    int cg = tid % 20, rg = tid / 20;
    float accp[8][5], accs[8][5];
#pragma unroll
    for (int i = 0; i < 8; i++)
#pragma unroll
        for (int j = 0; j < 5; j++) { accp[i][j] = 0.f; accs[i][j] = 0.f; }

#pragma unroll 2
    for (int k = 0; k < D1; k++) {
        float wn[5], ws[5];
#pragma unroll
        for (int j = 0; j < 5; j++) {
            wn[j] = __ldg(&Wn[k * D2 + cg + 20 * j]);
            ws[j] = __ldg(&Ws[k * D2 + cg + 20 * j]);
        }
#pragma unroll
        for (int i = 0; i < 8; i++) {
            float av = as[(rg * 8 + i) * D1P + k];
#pragma unroll
            for (int j = 0; j < 5; j++) {
                accp[i][j] = fmaf(av, wn[j], accp[i][j]);
                accs[i][j] = fmaf(av, ws[j], accs[i][j]);
            }
        }
    }
#pragma unroll
    for (int i = 0; i < 8; i++) {
        int g = row0 + rg * 8 + i;
        if (g >= N_NODES) continue;
#pragma unroll
        for (int j = 0; j < 5; j++) {
            int c = cg + 20 * j;
            g_p[(size_t)g * D2 + c] = accp[i][j];
            g_s[(size_t)g * D2 + c] = accs[i][j];
        }
    }
}

// ---------------- gather 2 + SAGE epilogue: h2 = ELU(s + mean(p) + b2) -------
__global__ void gather2_kernel(const float* __restrict__ b2) {
    int w    = (blockIdx.x * blockDim.x + threadIdx.x) >> 5;
    int lane = threadIdx.x & 31;
    if (w >= N_NODES) return;
    int beg = g_rowoff[w];
    int cnt = g_deg_in_i[w];
    bool act = lane < (D2 / 4);   // 25 active data lanes
    float4 acc = make_float4(0.f, 0.f, 0.f, 0.f);
    for (int base = 0; base < cnt; base += 32) {
        int idx = base + lane;
        int s = (idx < cnt) ? g_csr[beg + idx] : 0;
        int m = min(32, cnt - base);
        for (int j = 0; j < m; j++) {
            int sj = __shfl_sync(0xffffffffu, s, j);
            if (act) {
                float4 v = __ldg((const float4*)(g_p + (size_t)sj * D2) + lane);
                acc.x += v.x; acc.y += v.y; acc.z += v.z; acc.w += v.w;
            }
        }
    }
    if (act) {
        float invd = 1.f / fmaxf((float)cnt, 1.f);
        float4 sv = *(const float4*)(g_s + (size_t)w * D2 + lane * 4);
        float4 bv = *(const float4*)(b2 + lane * 4);
        float4 o;
        o.x = elu(acc.x * invd + sv.x + bv.x);
        o.y = elu(acc.y * invd + sv.y + bv.y);
        o.z = elu(acc.z * invd + sv.z + bv.z);
        o.w = elu(acc.w * invd + sv.w + bv.w);
        *(float4*)(g_h2 + (size_t)w * D2 + lane * 4) = o;
    }
}

// ---------------- GEMM3: out = ELU(h2 @ W3 + b3)  [N,100]->[N,64] ------------
__global__ __launch_bounds__(256) void gemm3_kernel(const float* __restrict__ W3,
                                                    const float* __restrict__ b3,
                                                    float* __restrict__ out) {
    __shared__ float as[64 * D2];
    int tid = threadIdx.x;
    int row0 = blockIdx.x * 64;
    for (int idx = tid; idx < 64 * (D2 / 4); idx += 256) {
        int r = idx / 25, c4 = idx % 25;
        int g = row0 + r;
        float4 v = make_float4(0.f, 0.f, 0.f, 0.f);
        if (g < N_NODES) v = ((const float4*)(g_h2 + (size_t)g * D2))[c4];
        *(float4*)&as[r * D2 + c4 * 4] = v;
    }
    __syncthreads();
    int cg = tid % 16, rg = tid / 16;
    float acc[4][4];
#pragma unroll
    for (int i = 0; i < 4; i++)
#pragma unroll
        for (int j = 0; j < 4; j++) acc[i][j] = 0.f;

#pragma unroll 4
    for (int k = 0; k < D2; k++) {
        float wv[4];
#pragma unroll
        for (int j = 0; j < 4; j++) wv[j] = __ldg(&W3[k * D_OUT + cg + 16 * j]);
#pragma unroll
        for (int i = 0; i < 4; i++) {
            float av = as[(rg * 4 + i) * D2 + k];
#pragma unroll
            for (int j = 0; j < 4; j++) acc[i][j] = fmaf(av, wv[j], acc[i][j]);
        }
    }
#pragma unroll
    for (int i = 0; i < 4; i++) {
        int g = row0 + rg * 4 + i;
        if (g >= N_NODES) continue;
#pragma unroll
        for (int j = 0; j < 4; j++) {
            int c = cg + 16 * j;
            out[(size_t)g * D_OUT + c] = elu(acc[i][j] + b3[c]);
        }
    }
}

// ---------------- launch -----------------------------------------------------
extern "C" void kernel_launch(void* const* d_in, const int* in_sizes, int n_in,
                              void* d_out, int out_size) {
    const float* x   = (const float*)d_in[0];
    const int*   src = (const int*)d_in[1];
    const int*   dst = (const int*)d_in[2];
    const float* W1  = (const float*)d_in[3];
    const float* b1  = (const float*)d_in[4];
    const float* Wn  = (const float*)d_in[5];
    const float* Ws  = (const float*)d_in[6];
    const float* b2  = (const float*)d_in[7];
    const float* W3  = (const float*)d_in[8];
    const float* b3  = (const float*)d_in[9];
    float* out = (float*)d_out;

    const int ROW_BLOCKS  = (N_NODES + 63) / 64;        // 782
    const int EDGE_BLOCKS = (N_EDGES + 255) / 256;      // 3125
    const int WARP_BLOCKS = (N_NODES * 32 + 255) / 256; // 6250

    zero_kernel<<<64, 256>>>();
    degree_kernel<<<EDGE_BLOCKS, 256>>>(src, dst);
    rowoff_kernel<<<(N_NODES + 255) / 256, 256>>>();
    bucket_kernel<<<EDGE_BLOCKS, 256>>>(src, dst);
    gather1_kernel<<<WARP_BLOCKS, 256>>>(x);
    gemm1_kernel<<<ROW_BLOCKS, 240>>>(W1, b1);
    gemm2_kernel<<<ROW_BLOCKS, 160>>>(Wn, Ws);
    gather2_kernel<<<WARP_BLOCKS, 256>>>(b2);
    gemm3_kernel<<<ROW_BLOCKS, 256>>>(W3, b3, out);
}

// round 7
// speedup vs baseline: 1.5414x; 1.0169x over previous
#include <cuda_runtime.h>
#include <math.h>

#define N_NODES 50000
#define N_EDGES 800000
#define D_IN    128
#define D1      150
#define D1P     152
#define D2      100
#define D_OUT   64

// ---------------- scratch (device globals) -----------------------------------
__device__ int   g_deg_out_i[N_NODES];
__device__ int   g_deg_in_i [N_NODES];
__device__ int   g_rowoff[N_NODES];
__device__ int   g_fill  [N_NODES];
__device__ int   g_total;
__device__ int   g_csr[N_EDGES];
__device__ float g_norm_out[N_NODES];

__device__ float g_agg[(size_t)N_NODES * D_IN];   // (A x) * norms, ready for W1
__device__ float g_h1 [(size_t)N_NODES * D1P];    // ELU(GraphConv), padded 152
__device__ float g_p  [(size_t)N_NODES * D2];     // h1 @ Wn
__device__ float g_s  [(size_t)N_NODES * D2];     // h1 @ Ws
__device__ float g_h2 [(size_t)N_NODES * D2];     // SAGE output

__device__ __forceinline__ float elu(float v) { return v > 0.f ? v : expm1f(v); }

// ---------------- zero counters ----------------------------------------------
__global__ void zero_kernel() {
    int stride = gridDim.x * blockDim.x;
    for (int i = blockIdx.x * blockDim.x + threadIdx.x; i < N_NODES; i += stride) {
        g_deg_out_i[i] = 0;
        g_deg_in_i[i]  = 0;
    }
    if (blockIdx.x == 0 && threadIdx.x == 0) g_total = 0;
}

// ---------------- degrees ----------------------------------------------------
__global__ void degree_kernel(const int* __restrict__ src, const int* __restrict__ dst) {
    int i = blockIdx.x * blockDim.x + threadIdx.x;
    if (i < N_EDGES) {
        atomicAdd(&g_deg_out_i[src[i]], 1);
        atomicAdd(&g_deg_in_i [dst[i]], 1);
    }
}

// ---------------- row offsets via warp-aggregated atomic ---------------------
__global__ void rowoff_kernel() {
    int i = blockIdx.x * blockDim.x + threadIdx.x;
    int lane = threadIdx.x & 31;
    int d = (i < N_NODES) ? g_deg_in_i[i] : 0;
    int x = d;
#pragma unroll
    for (int off = 1; off < 32; off <<= 1) {
        int t = __shfl_up_sync(0xffffffffu, x, off);
        if (lane >= off) x += t;
    }
    int excl = x - d;
    int total = __shfl_sync(0xffffffffu, x, 31);
    int base = 0;
    if (lane == 0) base = atomicAdd(&g_total, total);
    base = __shfl_sync(0xffffffffu, base, 0);
    if (i < N_NODES) {
        int o = base + excl;
        g_rowoff[i] = o;
        g_fill[i]   = o;
        g_norm_out[i] = rsqrtf(fmaxf((float)g_deg_out_i[i], 1.f));
    }
}

__global__ void bucket_kernel(const int* __restrict__ src, const int* __restrict__ dst) {
    int i = blockIdx.x * blockDim.x + threadIdx.x;
    if (i < N_EDGES) {
        int pos = atomicAdd(&g_fill[dst[i]], 1);
        g_csr[pos] = src[i];
    }
}

// ---------------- gather 1: agg[d] = norm_in[d] * sum x[s]*norm_out[s] -------
// one warp per node, lane handles 4 contiguous floats of the 128-float row
__global__ void gather1_kernel(const float* __restrict__ x) {
    int w    = (blockIdx.x * blockDim.x + threadIdx.x) >> 5;
    int lane = threadIdx.x & 31;
    if (w >= N_NODES) return;
    int beg = g_rowoff[w];
    int cnt = g_deg_in_i[w];
    float4 acc = make_float4(0.f, 0.f, 0.f, 0.f);
    for (int base = 0; base < cnt; base += 32) {
        int idx = base + lane;
        int s = 0; float ns = 0.f;
        if (idx < cnt) { s = g_csr[beg + idx]; ns = g_norm_out[s]; }
        int m = min(32, cnt - base);
        for (int j = 0; j < m; j++) {
            int   sj  = __shfl_sync(0xffffffffu, s,  j);
            float nsj = __shfl_sync(0xffffffffu, ns, j);
            float4 v = __ldg((const float4*)(x + (size_t)sj * D_IN) + lane);
            acc.x = fmaf(v.x, nsj, acc.x);
            acc.y = fmaf(v.y, nsj, acc.y);
            acc.z = fmaf(v.z, nsj, acc.z);
            acc.w = fmaf(v.w, nsj, acc.w);
        }
    }
    float nin = rsqrtf(fmaxf((float)cnt, 1.f));
    acc.x *= nin; acc.y *= nin; acc.z *= nin; acc.w *= nin;
    ((float4*)(g_agg + (size_t)w * D_IN))[lane] = acc;
}

// ---------------- GEMM1: h1 = ELU(agg @ W1 + b1)  [N,128]->[N,150] -----------
__global__ __launch_bounds__(240, 3) void gemm1_kernel(const float* __restrict__ W1,
                                                       const float* __restrict__ b1) {
    __shared__ float as[64 * 132];
    int tid = threadIdx.x;
    int row0 = blockIdx.x * 64;
    for (int idx = tid; idx < 64 * (D_IN / 4); idx += 240) {
        int r = idx >> 5, c4 = idx & 31;
        int g = row0 + r;
        float4 v = make_float4(0.f, 0.f, 0.f, 0.f);
        if (g < N_NODES) v = ((const float4*)(g_agg + (size_t)g * D_IN))[c4];
        *(float4*)&as[r * 132 + (c4 << 2)] = v;
    }
    __syncthreads();
    int cg = tid % 30, rg = tid / 30;
    float acc[8][5];
#pragma unroll
    for (int i = 0; i < 8; i++)
#pragma unroll
        for (int j = 0; j < 5; j++) acc[i][j] = 0.f;

#pragma unroll 4
    for (int k = 0; k < D_IN; k++) {
        float wv[5];
#pragma unroll
        for (int j = 0; j < 5; j++) wv[j] = __ldg(&W1[k * D1 + cg + 30 * j]);
#pragma unroll
        for (int i = 0; i < 8; i++) {
            float av = as[(rg * 8 + i) * 132 + k];
#pragma unroll
            for (int j = 0; j < 5; j++) acc[i][j] = fmaf(av, wv[j], acc[i][j]);
        }
    }
#pragma unroll
    for (int i = 0; i < 8; i++) {
        int g = row0 + rg * 8 + i;
        if (g >= N_NODES) continue;
#pragma unroll
        for (int j = 0; j < 5; j++) {
            int c = cg + 30 * j;
            g_h1[(size_t)g * D1P + c] = elu(acc[i][j] + b1[c]);
        }
    }
}

// ---------------- GEMM2 merged: p = h1@Wn, s = h1@Ws  [N,150]->[N,100]x2 -----
// A-tile in smem (loaded once for BOTH products), W streamed via __ldg
// 160 thr: rg 8 x cg 20, TM=8, TN=5 per product
__global__ __launch_bounds__(160, 3) void gemm2_kernel(const float* __restrict__ Wn,
                                                       const float* __restrict__ Ws) {
    __shared__ float as[64 * D1P];
    int tid = threadIdx.x;
    int row0 = blockIdx.x * 64;
    for (int idx = tid; idx < 64 * (D1P / 4); idx += 160) {
        int r = idx / 38, c4 = idx % 38;
        int g = row0 + r;
        float4 v = make_float4(0.f, 0.f, 0.f, 0.f);
        if (g < N_NODES) v = ((const float4*)(g_h1 + (size_t)g * D1P))[c4];
        *(float4*)&as[r * D1P + c4 * 4] = v;
    }
    __syncthreads();
    int cg = tid % 20, rg = tid / 20;
    float accp[8][5], accs[8][5];
#pragma unroll
    for (int i = 0; i < 8; i++)
#pragma unroll
        for (int j = 0; j < 5; j++) { accp[i][j] = 0.f; accs[i][j] = 0.f; }

#pragma unroll 2
    for (int k = 0; k < D1; k++) {
        float wn[5], ws[5];
#pragma unroll
        for (int j = 0; j < 5; j++) {
            wn[j] = __ldg(&Wn[k * D2 + cg + 20 * j]);
            ws[j] = __ldg(&Ws[k * D2 + cg + 20 * j]);
        }
#pragma unroll
        for (int i = 0; i < 8; i++) {
            float av = as[(rg * 8 + i) * D1P + k];
#pragma unroll
            for (int j = 0; j < 5; j++) {
                accp[i][j] = fmaf(av, wn[j], accp[i][j]);
                accs[i][j] = fmaf(av, ws[j], accs[i][j]);
            }
        }
    }
#pragma unroll
    for (int i = 0; i < 8; i++) {
        int g = row0 + rg * 8 + i;
        if (g >= N_NODES) continue;
#pragma unroll
        for (int j = 0; j < 5; j++) {
            int c = cg + 20 * j;
            g_p[(size_t)g * D2 + c] = accp[i][j];
            g_s[(size_t)g * D2 + c] = accs[i][j];
        }
    }
}

// ---------------- gather 2 + SAGE epilogue: h2 = ELU(s + mean(p) + b2) -------
__global__ void gather2_kernel(const float* __restrict__ b2) {
    int w    = (blockIdx.x * blockDim.x + threadIdx.x) >> 5;
    int lane = threadIdx.x & 31;
    if (w >= N_NODES) return;
    int beg = g_rowoff[w];
    int cnt = g_deg_in_i[w];
    bool act = lane < (D2 / 4);   // 25 active data lanes
    float4 acc = make_float4(0.f, 0.f, 0.f, 0.f);
    for (int base = 0; base < cnt; base += 32) {
        int idx = base + lane;
        int s = (idx < cnt) ? g_csr[beg + idx] : 0;
        int m = min(32, cnt - base);
        for (int j = 0; j < m; j++) {
            int sj = __shfl_sync(0xffffffffu, s, j);
            if (act) {
                float4 v = __ldg((const float4*)(g_p + (size_t)sj * D2) + lane);
                acc.x += v.x; acc.y += v.y; acc.z += v.z; acc.w += v.w;
            }
        }
    }
    if (act) {
        float invd = 1.f / fmaxf((float)cnt, 1.f);
        float4 sv = *(const float4*)(g_s + (size_t)w * D2 + lane * 4);
        float4 bv = *(const float4*)(b2 + lane * 4);
        float4 o;
        o.x = elu(acc.x * invd + sv.x + bv.x);
        o.y = elu(acc.y * invd + sv.y + bv.y);
        o.z = elu(acc.z * invd + sv.z + bv.z);
        o.w = elu(acc.w * invd + sv.w + bv.w);
        *(float4*)(g_h2 + (size_t)w * D2 + lane * 4) = o;
    }
}

// ---------------- GEMM3: out = ELU(h2 @ W3 + b3)  [N,100]->[N,64] ------------
// 128 thr: rg 8 x cg 16, TM=8, TN=4
__global__ __launch_bounds__(128) void gemm3_kernel(const float* __restrict__ W3,
                                                    const float* __restrict__ b3,
                                                    float* __restrict__ out) {
    __shared__ float as[64 * D2];
    int tid = threadIdx.x;
    int row0 = blockIdx.x * 64;
    for (int idx = tid; idx < 64 * (D2 / 4); idx += 128) {
        int r = idx / 25, c4 = idx % 25;
        int g = row0 + r;
        float4 v = make_float4(0.f, 0.f, 0.f, 0.f);
        if (g < N_NODES) v = ((const float4*)(g_h2 + (size_t)g * D2))[c4];
        *(float4*)&as[r * D2 + c4 * 4] = v;
    }
    __syncthreads();
    int cg = tid % 16, rg = tid / 16;
    float acc[8][4];
#pragma unroll
    for (int i = 0; i < 8; i++)
#pragma unroll
        for (int j = 0; j < 4; j++) acc[i][j] = 0.f;

#pragma unroll 4
    for (int k = 0; k < D2; k++) {
        float wv[4];
#pragma unroll
        for (int j = 0; j < 4; j++) wv[j] = __ldg(&W3[k * D_OUT + cg + 16 * j]);
#pragma unroll
        for (int i = 0; i < 8; i++) {
            float av = as[(rg * 8 + i) * D2 + k];
#pragma unroll
            for (int j = 0; j < 4; j++) acc[i][j] = fmaf(av, wv[j], acc[i][j]);
        }
    }
#pragma unroll
    for (int i = 0; i < 8; i++) {
        int g = row0 + rg * 8 + i;
        if (g >= N_NODES) continue;
#pragma unroll
        for (int j = 0; j < 4; j++) {
            int c = cg + 16 * j;
            out[(size_t)g * D_OUT + c] = elu(acc[i][j] + b3[c]);
        }
    }
}

// ---------------- launch -----------------------------------------------------
extern "C" void kernel_launch(void* const* d_in, const int* in_sizes, int n_in,
                              void* d_out, int out_size) {
    const float* x   = (const float*)d_in[0];
    const int*   src = (const int*)d_in[1];
    const int*   dst = (const int*)d_in[2];
    const float* W1  = (const float*)d_in[3];
    const float* b1  = (const float*)d_in[4];
    const float* Wn  = (const float*)d_in[5];
    const float* Ws  = (const float*)d_in[6];
    const float* b2  = (const float*)d_in[7];
    const float* W3  = (const float*)d_in[8];
    const float* b3  = (const float*)d_in[9];
    float* out = (float*)d_out;

    const int ROW_BLOCKS  = (N_NODES + 63) / 64;        // 782
    const int EDGE_BLOCKS = (N_EDGES + 255) / 256;      // 3125
    const int WARP_BLOCKS = (N_NODES * 32 + 255) / 256; // 6250

    zero_kernel<<<64, 256>>>();
    degree_kernel<<<EDGE_BLOCKS, 256>>>(src, dst);
    rowoff_kernel<<<(N_NODES + 255) / 256, 256>>>();
    bucket_kernel<<<EDGE_BLOCKS, 256>>>(src, dst);
    gather1_kernel<<<WARP_BLOCKS, 256>>>(x);
    gemm1_kernel<<<ROW_BLOCKS, 240>>>(W1, b1);
    gemm2_kernel<<<ROW_BLOCKS, 160>>>(Wn, Ws);
    gather2_kernel<<<WARP_BLOCKS, 256>>>(b2);
    gemm3_kernel<<<ROW_BLOCKS, 128>>>(W3, b3, out);
}